// round 5
// baseline (speedup 1.0000x reference)
#include <cuda_runtime.h>
#include <cstdint>

#define DIM 128
#define MAX_N 50000
#define MAX_E 800000

// ---------------------------------------------------------------------------
// Scratch (static __device__ arrays; no allocation)
// ---------------------------------------------------------------------------
__device__ int  g_counts[MAX_N];
__device__ int  g_offsets[MAX_N + 1];
__device__ int  g_cursors[MAX_N];
__device__ int2 g_sorted[MAX_E];   // {src, eid} sorted by dst

// ---------------------------------------------------------------------------
// Kernel 1: zero counts
// ---------------------------------------------------------------------------
__global__ void zero_counts_kernel(int n) {
    int i = blockIdx.x * blockDim.x + threadIdx.x;
    if (i < n) g_counts[i] = 0;
}

// ---------------------------------------------------------------------------
// Kernel 2: histogram of dst
// ---------------------------------------------------------------------------
__global__ void hist_kernel(const int* __restrict__ edge_index, int E) {
    int e = blockIdx.x * blockDim.x + threadIdx.x;
    if (e >= E) return;
    int dst = edge_index[E + e];
    atomicAdd(&g_counts[dst], 1);
}

// ---------------------------------------------------------------------------
// Kernel 3: exclusive scan of counts (single block, 1024 threads)
// ---------------------------------------------------------------------------
__global__ void scan_kernel(int n, int E) {
    __shared__ int part[1024];
    int tid = threadIdx.x;
    int chunk = (n + 1023) >> 10;
    int beg = tid * chunk;
    int end = beg + chunk; if (end > n) end = n;
    int s = 0;
    for (int i = beg; i < end; i++) s += g_counts[i];
    part[tid] = s;
    __syncthreads();
    // inclusive Hillis-Steele scan over 1024 partials
    for (int d = 1; d < 1024; d <<= 1) {
        int v = (tid >= d) ? part[tid - d] : 0;
        __syncthreads();
        part[tid] += v;
        __syncthreads();
    }
    int run = part[tid] - s;   // exclusive base for this thread's chunk
    for (int i = beg; i < end; i++) {
        g_offsets[i] = run;
        g_cursors[i] = run;
        run += g_counts[i];
    }
    if (tid == 0) g_offsets[n] = E;
}

// ---------------------------------------------------------------------------
// Kernel 4: scatter {src, eid} into dst-sorted order
// ---------------------------------------------------------------------------
__global__ void scatter_kernel(const int* __restrict__ edge_index, int E) {
    int e = blockIdx.x * blockDim.x + threadIdx.x;
    if (e >= E) return;
    int src = edge_index[e];
    int dst = edge_index[E + e];
    int pos = atomicAdd(&g_cursors[dst], 1);
    g_sorted[pos] = make_int2(src, e);
}

// ---------------------------------------------------------------------------
// Kernel 5: aggregate. One warp per node; lane l owns float4 chunk l.
//   acc = sum over in-edges of relu(node_feat[src] + edge_feat[eid])
//   out[node] = (1+eps)*node_feat[node] + acc        (single coalesced write)
// No float atomics anywhere.
// ---------------------------------------------------------------------------
__device__ __forceinline__ float4 ld_evict_last(const float* p, unsigned long long pol) {
    float4 a;
    asm volatile("ld.global.nc.L2::cache_hint.v4.f32 {%0, %1, %2, %3}, [%4], %5;"
                 : "=f"(a.x), "=f"(a.y), "=f"(a.z), "=f"(a.w)
                 : "l"(p), "l"(pol));
    return a;
}
__device__ __forceinline__ float4 ld_stream(const float* p) {
    float4 b;
    asm volatile("ld.global.cs.v4.f32 {%0, %1, %2, %3}, [%4];"
                 : "=f"(b.x), "=f"(b.y), "=f"(b.z), "=f"(b.w) : "l"(p));
    return b;
}

__global__ __launch_bounds__(256, 8)
void aggregate_kernel(const float* __restrict__ node_feat,
                      const float* __restrict__ edge_feat,
                      const float* __restrict__ eps,
                      float* __restrict__ out,
                      int N) {
    int warp = (blockIdx.x * blockDim.x + threadIdx.x) >> 5;
    int lane = threadIdx.x & 31;
    if (warp >= N) return;
    int node = warp;

    unsigned long long pol;
    asm volatile("createpolicy.fractional.L2::evict_last.b64 %0, 1.0;"
                 : "=l"(pol));

    int beg = g_offsets[node];
    int end = g_offsets[node + 1];

    // self term issued early to overlap with edge loop
    float4 self = ld_evict_last(node_feat + (long long)node * DIM + lane * 4, pol);
    float s = 1.0f + eps[0];

    float4 acc0 = make_float4(0.f, 0.f, 0.f, 0.f);
    float4 acc1 = make_float4(0.f, 0.f, 0.f, 0.f);

    int i = beg;
    for (; i + 1 < end; i += 2) {
        int2 e0 = g_sorted[i];
        int2 e1 = g_sorted[i + 1];
        float4 a0 = ld_evict_last(node_feat + (long long)e0.x * DIM + lane * 4, pol);
        float4 b0 = ld_stream(edge_feat + (long long)e0.y * DIM + lane * 4);
        float4 a1 = ld_evict_last(node_feat + (long long)e1.x * DIM + lane * 4, pol);
        float4 b1 = ld_stream(edge_feat + (long long)e1.y * DIM + lane * 4);
        acc0.x += fmaxf(a0.x + b0.x, 0.f);
        acc0.y += fmaxf(a0.y + b0.y, 0.f);
        acc0.z += fmaxf(a0.z + b0.z, 0.f);
        acc0.w += fmaxf(a0.w + b0.w, 0.f);
        acc1.x += fmaxf(a1.x + b1.x, 0.f);
        acc1.y += fmaxf(a1.y + b1.y, 0.f);
        acc1.z += fmaxf(a1.z + b1.z, 0.f);
        acc1.w += fmaxf(a1.w + b1.w, 0.f);
    }
    if (i < end) {
        int2 e0 = g_sorted[i];
        float4 a0 = ld_evict_last(node_feat + (long long)e0.x * DIM + lane * 4, pol);
        float4 b0 = ld_stream(edge_feat + (long long)e0.y * DIM + lane * 4);
        acc0.x += fmaxf(a0.x + b0.x, 0.f);
        acc0.y += fmaxf(a0.y + b0.y, 0.f);
        acc0.z += fmaxf(a0.z + b0.z, 0.f);
        acc0.w += fmaxf(a0.w + b0.w, 0.f);
    }

    float4 r;
    r.x = fmaf(s, self.x, acc0.x + acc1.x);
    r.y = fmaf(s, self.y, acc0.y + acc1.y);
    r.z = fmaf(s, self.z, acc0.z + acc1.z);
    r.w = fmaf(s, self.w, acc0.w + acc1.w);
    reinterpret_cast<float4*>(out + (long long)node * DIM)[lane] = r;
}

// ---------------------------------------------------------------------------
// Launch
// inputs (metadata order): node_feat (N*D f32), edge_index (2*E i32),
//                          edge_feat (E*D f32), eps (1 f32)
// output: (N, D) float32
// ---------------------------------------------------------------------------
extern "C" void kernel_launch(void* const* d_in, const int* in_sizes, int n_in,
                              void* d_out, int out_size) {
    const float* node_feat = (const float*)d_in[0];
    const int* edge_index = (const int*)d_in[1];
    const float* edge_feat = (const float*)d_in[2];
    const float* eps = (const float*)d_in[3];
    float* out = (float*)d_out;

    int N = in_sizes[0] / DIM;
    int E = in_sizes[1] / 2;

    zero_counts_kernel<<<(N + 255) / 256, 256>>>(N);
    hist_kernel<<<(E + 255) / 256, 256>>>(edge_index, E);
    scan_kernel<<<1, 1024>>>(N, E);
    scatter_kernel<<<(E + 255) / 256, 256>>>(edge_index, E);

    long long agg_threads = (long long)N * 32;
    int agg_blocks = (int)((agg_threads + 255) / 256);
    aggregate_kernel<<<agg_blocks, 256>>>(node_feat, edge_feat, eps, out, N);
}

// round 6
// speedup vs baseline: 1.7517x; 1.7517x over previous
#include <cuda_runtime.h>
#include <cstdint>

#define DIM 128
#define EDGES_PER_WARP 32

// ---------------------------------------------------------------------------
// Kernel 1: out[i] = (1 + eps) * node_feat[i]   (vectorized float4)
// ---------------------------------------------------------------------------
__global__ void gine_init_kernel(const float* __restrict__ node_feat,
                                 const float* __restrict__ eps,
                                 float* __restrict__ out,
                                 int total4) {
    int i = blockIdx.x * blockDim.x + threadIdx.x;
    if (i >= total4) return;
    float s = 1.0f + eps[0];
    float4 v = reinterpret_cast<const float4*>(node_feat)[i];
    v.x *= s; v.y *= s; v.z *= s; v.w *= s;
    reinterpret_cast<float4*>(out)[i] = v;
}

// ---------------------------------------------------------------------------
// Helpers: cache-policy loads
// ---------------------------------------------------------------------------
__device__ __forceinline__ float4 ld_evict_last(const float* p, unsigned long long pol) {
    float4 a;
    asm volatile("ld.global.nc.L2::cache_hint.v4.f32 {%0, %1, %2, %3}, [%4], %5;"
                 : "=f"(a.x), "=f"(a.y), "=f"(a.z), "=f"(a.w)
                 : "l"(p), "l"(pol));
    return a;
}
__device__ __forceinline__ float4 ld_stream(const float* p) {
    float4 b;
    asm volatile("ld.global.cs.v4.f32 {%0, %1, %2, %3}, [%4];"
                 : "=f"(b.x), "=f"(b.y), "=f"(b.z), "=f"(b.w) : "l"(p));
    return b;
}

// ---------------------------------------------------------------------------
// Kernel 2: 32 edges per warp.
//   - lane loads src/dst for edge (base+lane): 2 coalesced loads replace 64
//     scalar index loads
//   - loop k over the 32 edges, indices broadcast via shfl
//   - edge_feat reads stream 16KB contiguous per warp
//   - scatter via red.global.add.v4.f32 (the irreducible cost)
// ---------------------------------------------------------------------------
__global__ __launch_bounds__(256, 8)
void gine_edge_kernel(const float* __restrict__ node_feat,
                      const int* __restrict__ edge_index,
                      const float* __restrict__ edge_feat,
                      float* __restrict__ out,
                      int num_edges) {
    int warp_global = (blockIdx.x * blockDim.x + threadIdx.x) >> 5;
    int lane = threadIdx.x & 31;

    long long e_base = (long long)warp_global * EDGES_PER_WARP;
    if (e_base >= num_edges) return;

    int cnt = num_edges - e_base < EDGES_PER_WARP ? (int)(num_edges - e_base)
                                                  : EDGES_PER_WARP;

    unsigned long long pol;
    asm volatile("createpolicy.fractional.L2::evict_last.b64 %0, 1.0;"
                 : "=l"(pol));

    // Coalesced index loads: lane l takes edge e_base + l.
    int my_e = (int)e_base + lane;
    int src_l = 0, dst_l = 0;
    if (lane < cnt) {
        asm volatile("ld.global.cs.b32 %0, [%1];" : "=r"(src_l)
                     : "l"(edge_index + my_e));
        asm volatile("ld.global.cs.b32 %0, [%1];" : "=r"(dst_l)
                     : "l"(edge_index + num_edges + my_e));
    }

    const float* ef_base = edge_feat + e_base * DIM + lane * 4;

    #pragma unroll 4
    for (int k = 0; k < cnt; k++) {
        int s = __shfl_sync(0xffffffffu, src_l, k);
        int d = __shfl_sync(0xffffffffu, dst_l, k);

        float4 a = ld_evict_last(node_feat + (long long)s * DIM + lane * 4, pol);
        float4 b = ld_stream(ef_base + (long long)k * DIM);

        float4 m;
        m.x = fmaxf(a.x + b.x, 0.0f);
        m.y = fmaxf(a.y + b.y, 0.0f);
        m.z = fmaxf(a.z + b.z, 0.0f);
        m.w = fmaxf(a.w + b.w, 0.0f);

        float* dptr = out + (long long)d * DIM + lane * 4;
        asm volatile("red.global.add.v4.f32 [%0], {%1, %2, %3, %4};"
                     :: "l"(dptr), "f"(m.x), "f"(m.y), "f"(m.z), "f"(m.w)
                     : "memory");
    }
}

// ---------------------------------------------------------------------------
// Launch
// inputs (metadata order): node_feat (N*D f32), edge_index (2*E i32),
//                          edge_feat (E*D f32), eps (1 f32)
// output: (N, D) float32
// ---------------------------------------------------------------------------
extern "C" void kernel_launch(void* const* d_in, const int* in_sizes, int n_in,
                              void* d_out, int out_size) {
    const float* node_feat = (const float*)d_in[0];
    const int* edge_index = (const int*)d_in[1];
    const float* edge_feat = (const float*)d_in[2];
    const float* eps = (const float*)d_in[3];
    float* out = (float*)d_out;

    int N = in_sizes[0] / DIM;
    int E = in_sizes[1] / 2;

    // Phase 1: out = (1 + eps) * node_feat
    int total4 = N * (DIM / 4);
    {
        int threads = 256;
        int blocks = (total4 + threads - 1) / threads;
        gine_init_kernel<<<blocks, threads>>>(node_feat, eps, out, total4);
    }

    // Phase 2: edge scatter, 32 edges per warp
    {
        int threads = 256;  // 8 warps/block
        long long num_warps = ((long long)E + EDGES_PER_WARP - 1) / EDGES_PER_WARP;
        int blocks = (int)((num_warps * 32 + threads - 1) / threads);
        gine_edge_kernel<<<blocks, threads>>>(node_feat, edge_index, edge_feat,
                                              out, E);
    }
}